// round 3
// baseline (speedup 1.0000x reference)
#include <cuda_runtime.h>
#include <cstdint>
#include <cstddef>

// CTC loss (faithful to reference incl. input_len = C bug).
// B=512, T=512 (row stride), C=128, Tu=128, L=64, S=129, blank=127.
// One warp per batch row; lane holds states 4*lane+j (j=0..3), lane31 also 128.
// Linear-domain recursion + power-of-2 rescale every 8 steps (REDUX max).
// Probability rows staged coalesced via cp.async (1 float4/lane = 512B/row),
// consumed via LDS. 4-step chunks, depth-2 async pipeline, 1 syncwarp/chunk.

#define B_    512
#define T_    512
#define C_    128
#define L_    64
#define TU    128
#define BLANK 127
#define EPSF  (1e-7f)
#define LN2F  (0.69314718055994530942f)

#define WARPS  2            // warps per block
#define CHUNK  4            // timestep rows per chunk
#define NBUF   4            // staging buffers per warp
#define NCHUNK (TU / CHUNK) // 32

__device__ __forceinline__ void cpasync16(uint32_t saddr, const void* gptr) {
    asm volatile("cp.async.cg.shared.global [%0], [%1], 16;\n"
                 :: "r"(saddr), "l"(gptr));
}
__device__ __forceinline__ void cpasync_commit() {
    asm volatile("cp.async.commit_group;\n");
}
__device__ __forceinline__ void cpasync_wait2() {
    asm volatile("cp.async.wait_group 2;\n");
}

__global__ __launch_bounds__(WARPS * 32, 16)
void ctc_warp_kernel(const int* __restrict__ y_true,
                     const float* __restrict__ y_pred,
                     float* __restrict__ out)
{
    const unsigned FULL = 0xffffffffu;
    const int lane = threadIdx.x & 31;
    const int w    = threadIdx.x >> 5;
    const int b    = blockIdx.x * WARPS + w;

    // staging: [warp][buf][step][class]
    __shared__ float sm[WARPS][NBUF][CHUNK][C_];
    float (*my)[CHUNK][C_] = sm[w];
    const uint32_t smbase =
        (uint32_t)__cvta_generic_to_shared(&sm[w][0][0][0]);

    const float* __restrict__ row = y_pred + (size_t)b * T_ * C_;

    // labels: coalesced int2 (lane -> labels 2*lane, 2*lane+1)
    const int2 lpair = ((const int2*)(y_true + b * L_))[lane];
    const int l0 = lpair.x;
    const int l1 = lpair.y;
    const int lp = __shfl_up_sync(FULL, l1, 1);            // lab[2*lane-1]
    const float sk1 = (lane > 0 && l0 != lp) ? 1.f : 0.f;  // state 4l+1 skip
    const float sk3 = (l1 != l0) ? 1.f : 0.f;              // state 4l+3 skip

    // ---- stage chunks 0 and 1 ----------------------------------------------
    {
        const float* g = row + lane * 4;
        #pragma unroll
        for (int c = 0; c < 2; ++c) {
            #pragma unroll
            for (int j = 0; j < CHUNK; ++j)
                cpasync16(smbase + (uint32_t)((c * CHUNK + j) * C_ + lane * 4) * 4u,
                          g + (c * CHUNK + j) * C_);
            cpasync_commit();
        }
    }

    float a0 = 0.f, a1 = 0.f, a2 = 0.f, a3 = 0.f, a4 = 0.f;
    int etot = 0;

    for (int c = 0; c < NCHUNK; ++c) {
        // stage chunk c+2 (empty commit keeps group accounting aligned)
        if (c + 2 < NCHUNK) {
            const int buf = (c + 2) & (NBUF - 1);
            const float* g = row + (size_t)(c + 2) * CHUNK * C_ + lane * 4;
            #pragma unroll
            for (int j = 0; j < CHUNK; ++j)
                cpasync16(smbase + (uint32_t)((buf * CHUNK + j) * C_ + lane * 4) * 4u,
                          g + j * C_);
        }
        cpasync_commit();
        cpasync_wait2();          // chunk c resident
        __syncwarp();

        const int buf = c & (NBUF - 1);
        const float* srow = &my[buf][0][0];

        #pragma unroll
        for (int j = 0; j < CHUNK; ++j) {
            const float q0 = srow[j * C_ + l0]    + EPSF;
            const float q1 = srow[j * C_ + l1]    + EPSF;
            const float qB = srow[j * C_ + BLANK] + EPSF;

            if (c == 0 && j == 0) {
                // t = 0 init: alpha[0]=qB, alpha[1]=q0 at lane 0
                if (lane == 0) { a0 = qB; a1 = q0; }
                continue;
            }
            float n3 = __shfl_up_sync(FULL, a3, 1);   // state 4(l-1)+3 = s-1 / s-2
            if (lane == 0) n3 = 0.f;

            const float na0 = (a0 + n3) * qB;                    // s=4l (blank)
            const float na1 = fmaf(n3, sk1, a1 + a0) * q0;       // s=4l+1
            const float na2 = (a2 + a1) * qB;                    // s=4l+2 (blank)
            const float na3 = fmaf(a1, sk3, a3 + a2) * q1;       // s=4l+3
            const float na4 = (a4 + a3) * qB;                    // s=128 (lane31)
            a0 = na0; a1 = na1; a2 = na2; a3 = na3; a4 = na4;
        }

        // power-of-two rescale every 2 chunks (8 steps)
        if (c & 1) {
            float mv = fmaxf(fmaxf(a0, a1), fmaxf(fmaxf(a2, a3), a4));
            int mbits = __float_as_int(mv);          // alpha >= 0 -> monotonic
            int rbits;
            asm volatile("redux.sync.max.s32 %0, %1, 0xffffffff;\n"
                         : "=r"(rbits) : "r"(mbits));
            const int e = (rbits >> 23) - 127;
            const float sc = __int_as_float((127 - e) << 23);    // 2^-e
            a0 *= sc; a1 *= sc; a2 *= sc; a3 *= sc; a4 *= sc;
            etot += e;
        }
    }

    // loss = -( ln(alpha[127] + alpha[128]) + etot*ln2 )
    if (lane == 31) {
        const float s = a3 + a4;
        out[b] = -(__logf(s) + (float)etot * LN2F);
    }
}

extern "C" void kernel_launch(void* const* d_in, const int* in_sizes, int n_in,
                              void* d_out, int out_size)
{
    const int* y_true;
    const float* y_pred;
    if (n_in >= 2 && in_sizes[0] == B_ * L_) {
        y_true = (const int*)d_in[0];
        y_pred = (const float*)d_in[1];
    } else {
        y_true = (const int*)d_in[1];
        y_pred = (const float*)d_in[0];
    }
    float* out = (float*)d_out;

    ctc_warp_kernel<<<B_ / WARPS, WARPS * 32>>>(y_true, y_pred, out);
}

// round 4
// speedup vs baseline: 1.0810x; 1.0810x over previous
#include <cuda_runtime.h>
#include <cstdint>
#include <cstddef>

// CTC loss (faithful to reference incl. input_len = C bug).
// B=512, T=512 (row stride), C=128, Tu=128, L=64, S=129, blank=127.
// Warp per row; lane holds states 4*lane+j, lane31 also state 128.
// Linear domain + power-of-2 rescale per 8 steps. Uniform 128-step recursion
// from a0=1@lane0 (virtual init). q-values register-pipelined one chunk ahead;
// recursion body is pure FADD/FMUL/FMAF + 1 shfl. cp.async depth-3 staging.

#define B_    512
#define T_    512
#define C_    128
#define L_    64
#define BLANK 127
#define EPSF  (1e-7f)
#define LN2F  0.69314718055994530942f

#define WARPS  2
#define CHUNK  8
#define NBUF   4
#define NCHUNK 16        // 128 timesteps / CHUNK

__device__ __forceinline__ void cpasync16(uint32_t saddr, const void* g) {
    asm volatile("cp.async.cg.shared.global [%0], [%1], 16;" :: "r"(saddr), "l"(g));
}
__device__ __forceinline__ void cp_commit() { asm volatile("cp.async.commit_group;"); }
__device__ __forceinline__ void cp_wait2()  { asm volatile("cp.async.wait_group 2;"); }
__device__ __forceinline__ void cp_wait0()  { asm volatile("cp.async.wait_group 0;"); }

struct Q { float q0, q1, qB, p1, p3; };

__global__ __launch_bounds__(WARPS * 32)
void ctc_kernel(const int* __restrict__ y_true,
                const float* __restrict__ y_pred,
                float* __restrict__ out)
{
    const unsigned FULL = 0xffffffffu;
    const int lane = threadIdx.x & 31;
    const int w    = threadIdx.x >> 5;
    const int b    = blockIdx.x * WARPS + w;

    __shared__ float sm[WARPS][NBUF][CHUNK][C_];
    const uint32_t smbase = (uint32_t)__cvta_generic_to_shared(&sm[w][0][0][0]);

    const float* __restrict__ row = y_pred + (size_t)b * T_ * C_;

    // labels (coalesced int2): lane -> labels 2*lane, 2*lane+1
    const int2 lpair = ((const int2*)(y_true + b * L_))[lane];
    const int l0 = lpair.x, l1 = lpair.y;
    const int lp = __shfl_up_sync(FULL, l1, 1);
    const float sk1 = (lane > 0 && l0 != lp) ? 1.f : 0.f;
    const float sk3 = (l1 != l0) ? 1.f : 0.f;

    // ---- staging helpers ---------------------------------------------------
    auto stage = [&](int c) {
        const float* g = row + (size_t)c * CHUNK * C_ + lane * 4;
        const uint32_t s = smbase +
            (uint32_t)(((c & (NBUF - 1)) * CHUNK * C_ + lane * 4) * 4);
        #pragma unroll
        for (int j = 0; j < CHUNK; ++j)
            cpasync16(s + j * C_ * 4, g + j * C_);
        cp_commit();
    };
    auto ldq = [&](int c, Q* q) {
        const float* srow = &sm[w][c & (NBUF - 1)][0][0];
        #pragma unroll
        for (int j = 0; j < CHUNK; ++j) {
            q[j].q0 = srow[j * C_ + l0]    + EPSF;
            q[j].q1 = srow[j * C_ + l1]    + EPSF;
            q[j].qB = srow[j * C_ + BLANK] + EPSF;
            q[j].p1 = sk1 * q[j].q0;
            q[j].p3 = sk3 * q[j].q1;
        }
    };

    // ---- alpha state: virtual init (one uniform step reproduces t=0 init) --
    float a0 = (lane == 0) ? 1.f : 0.f;
    float a1 = 0.f, a2 = 0.f, a3 = 0.f, a4 = 0.f;
    float n3 = 0.f;             // neighbor a3 (pre-shfl'd for upcoming step)
    int etot = 0;

    auto steps = [&](const Q* q) {
        #pragma unroll
        for (int j = 0; j < CHUNK; ++j) {
            const float na0 = (a0 + n3) * q[j].qB;                // s=4l (blank)
            const float na1 = fmaf(a1 + a0, q[j].q0, q[j].p1 * n3);
            const float na2 = (a2 + a1) * q[j].qB;                // blank
            const float na3 = fmaf(a3 + a2, q[j].q1, q[j].p3 * a1);
            const float na4 = (a4 + a3) * q[j].qB;                // s=128
            a0 = na0; a1 = na1; a2 = na2; a3 = na3; a4 = na4;
            const float t = __shfl_up_sync(FULL, a3, 1);          // issued early
            n3 = (lane == 0) ? 0.f : t;
        }
        // power-of-two rescale (alpha >= 0 -> float bits monotonic as s32)
        float mv = fmaxf(fmaxf(a0, a1), fmaxf(fmaxf(a2, a3), a4));
        int rb;
        asm volatile("redux.sync.max.s32 %0, %1, 0xffffffff;"
                     : "=r"(rb) : "r"(__float_as_int(mv)));
        const int e = (rb >> 23) - 127;
        const float sc = __int_as_float((127 - e) << 23);         // 2^-e
        a0 *= sc; a1 *= sc; a2 *= sc; a3 *= sc; a4 *= sc; n3 *= sc;
        etot += e;
    };

    // ---- pipeline prologue --------------------------------------------------
    stage(0); stage(1); stage(2);
    cp_wait2(); __syncwarp();
    Q qa[CHUNK], qb[CHUNK];
    ldq(0, qa);

    // ---- main loop: chunk pairs (ping-pong register sets) -------------------
    for (int p = 0; p < NCHUNK / 2; ++p) {
        const int c = 2 * p;
        // body A: compute chunk c (qa), prefetch chunk c+1 -> qb
        if (c + 3 < NCHUNK) { stage(c + 3); cp_wait2(); } else { cp_wait0(); }
        __syncwarp();
        ldq(c + 1, qb);                 // c+1 <= 15 always here
        steps(qa);
        // body B: compute chunk c+1 (qb), prefetch chunk c+2 -> qa
        const int c2 = c + 1;
        if (c2 + 3 < NCHUNK) { stage(c2 + 3); cp_wait2(); } else { cp_wait0(); }
        __syncwarp();
        if (c2 + 1 < NCHUNK) ldq(c2 + 1, qa);
        steps(qb);
    }

    // ---- loss = -( ln(alpha[127] + alpha[128]) + etot*ln2 ) -----------------
    if (lane == 31) {
        const float s = a3 + a4;
        out[b] = -(__logf(s) + (float)etot * LN2F);
    }
}

extern "C" void kernel_launch(void* const* d_in, const int* in_sizes, int n_in,
                              void* d_out, int out_size)
{
    const int* y_true;
    const float* y_pred;
    if (n_in >= 2 && in_sizes[0] == B_ * L_) {
        y_true = (const int*)d_in[0];
        y_pred = (const float*)d_in[1];
    } else {
        y_true = (const int*)d_in[1];
        y_pred = (const float*)d_in[0];
    }
    float* out = (float*)d_out;

    ctc_kernel<<<B_ / WARPS, WARPS * 32>>>(y_true, y_pred, out);
}